// round 6
// baseline (speedup 1.0000x reference)
#include <cuda_runtime.h>

#define CC 20
#define NCELLS (16384 * 7 * 7)          // 802816
#define CELLS_PER_TILE 128
#define TILES_PER_BLOCK 7
#define NBLOCKS 896                     // 896 * 7 * 128 = 802816
#define PRED_STRIDE 30
#define TGT_STRIDE 25
#define LAMBDA_COORD 5.0f
#define LAMBDA_NOOBJ 0.5f
#define EPS_W 1e-6f
#define IOU_EPS 1e-6f
#define INV_BATCH (1.0 / 16384.0)

#define PRED_F4_PER_TILE (CELLS_PER_TILE * PRED_STRIDE / 4)   // 960
#define TGT_F4_PER_TILE  (CELLS_PER_TILE * TGT_STRIDE  / 4)   // 800

// Per-block partial sums: written unconditionally every launch -> no zeroing,
// no atomics, graph-replay idempotent.
__device__ double g_partial[NBLOCKS];

__device__ __forceinline__ float iou_box(float ax, float ay, float aw, float ah,
                                         float bx, float by, float bw, float bh) {
    float ax1 = ax - aw * 0.5f, ax2 = ax + aw * 0.5f;
    float ay1 = ay - ah * 0.5f, ay2 = ay + ah * 0.5f;
    float bx1 = bx - bw * 0.5f, bx2 = bx + bw * 0.5f;
    float by1 = by - bh * 0.5f, by2 = by + bh * 0.5f;
    float iw = fmaxf(fminf(ax2, bx2) - fmaxf(ax1, bx1), 0.0f);
    float ih = fmaxf(fminf(ay2, by2) - fmaxf(ay1, by1), 0.0f);
    float inter = iw * ih;
    float area_a = fabsf(aw * ah);
    float area_b = fabsf(bw * bh);
    return inter / (area_a + area_b - inter + IOU_EPS);
}

__global__ void __launch_bounds__(CELLS_PER_TILE)
yolo_loss_kernel(const float* __restrict__ pred, const float* __restrict__ tgt) {
    __shared__ float sp[CELLS_PER_TILE * PRED_STRIDE + 32];
    __shared__ float st[CELLS_PER_TILE * TGT_STRIDE + 32];

    const int tid = threadIdx.x;
    const int bid = blockIdx.x;

    float loss = 0.0f;

    #pragma unroll 1
    for (int tile = 0; tile < TILES_PER_BLOCK; tile++) {
        const size_t cell_base = ((size_t)bid * TILES_PER_BLOCK + tile) * CELLS_PER_TILE;

        // ---- Stage: fully coalesced float4 loads into smem ----
        {
            const float4* psrc = reinterpret_cast<const float4*>(
                pred + cell_base * PRED_STRIDE);
            float4* pdst = reinterpret_cast<float4*>(sp);
            #pragma unroll
            for (int i = tid; i < PRED_F4_PER_TILE; i += CELLS_PER_TILE)
                pdst[i] = psrc[i];

            const float4* tsrc = reinterpret_cast<const float4*>(
                tgt + cell_base * TGT_STRIDE);
            float4* tdst = reinterpret_cast<float4*>(st);
            #pragma unroll
            for (int i = tid; i < TGT_F4_PER_TILE; i += CELLS_PER_TILE)
                tdst[i] = tsrc[i];
        }
        __syncthreads();

        // ---- Compute: one thread = one cell, operands from smem ----
        const float* p = sp + tid * PRED_STRIDE;
        const float* t = st + tid * TGT_STRIDE;

        float cls = 0.0f;
        #pragma unroll
        for (int i = 0; i < CC; i++) {
            float d = p[i] - t[i];
            cls = fmaf(d, d, cls);
        }

        float b1x = p[20], b1y = p[21], b1w = p[22], b1h = p[23], b1c = p[24];
        float b2x = p[25], b2y = p[26], b2w = p[27], b2h = p[28], b2c = p[29];
        // tb = targets[..., 20:25] : note tb.x IS the objectness flag column
        float tbx = t[20], tby = t[21], tbw = t[22], tbh = t[23], tbc = t[24];
        float obj = (tbx == 1.0f) ? 1.0f : 0.0f;

        float iou1 = iou_box(b1x, b1y, b1w, b1h, tbx, tby, tbw, tbh);
        float iou2 = iou_box(b2x, b2y, b2w, b2h, tbx, tby, tbw, tbh);
        bool use1 = iou1 > iou2;

        float rx = use1 ? b1x : b2x;
        float ry = use1 ? b1y : b2y;
        float rw = use1 ? b1w : b2w;
        float rh = use1 ? b1h : b2h;
        float rc = use1 ? b1c : b2c;
        float other_conf = use1 ? b2c : b1c;

        float dx = rx - tbx;
        float dy = ry - tby;
        float dw = sqrtf(fmaxf(rw, EPS_W)) - sqrtf(fmaxf(tbw, EPS_W));
        float dh = sqrtf(fmaxf(rh, EPS_W)) - sqrtf(fmaxf(tbh, EPS_W));
        float coord = LAMBDA_COORD * (dx * dx + dy * dy + dw * dw + dh * dh);

        float dconf = rc - tbc;
        float obj_conf = dconf * dconf;
        float noobj_in = LAMBDA_NOOBJ * other_conf * other_conf;
        float noobj_out = LAMBDA_NOOBJ * (b1c * b1c + b2c * b2c);

        loss += obj * (coord + obj_conf + cls + noobj_in) + (1.0f - obj) * noobj_out;

        __syncthreads();   // smem reuse guard before next tile's stage
    }

    // ---- Block reduction (once, after all tiles) ----
    #pragma unroll
    for (int o = 16; o > 0; o >>= 1)
        loss += __shfl_xor_sync(0xffffffffu, loss, o);

    __shared__ float warp_sums[4];
    int lane = tid & 31;
    int wid = tid >> 5;
    if (lane == 0) warp_sums[wid] = loss;
    __syncthreads();

    if (wid == 0) {
        float s = (lane < 4) ? warp_sums[lane] : 0.0f;
        #pragma unroll
        for (int o = 2; o > 0; o >>= 1)
            s += __shfl_xor_sync(0xffffffffu, s, o);
        if (lane == 0)
            g_partial[bid] = (double)s;   // unconditional write, no atomic
    }
}

__global__ void __launch_bounds__(256)
finalize_kernel(float* out) {
    const int tid = threadIdx.x;

    // 896 partials / 256 threads: up to 4 INDEPENDENT loads per thread
    // (separate accumulators -> MLP=4, no serial chain).
    double a0 = g_partial[tid];
    double a1 = g_partial[tid + 256];
    double a2 = g_partial[tid + 512];
    double a3 = (tid < NBLOCKS - 768) ? g_partial[tid + 768] : 0.0;
    double s = (a0 + a1) + (a2 + a3);

    #pragma unroll
    for (int o = 16; o > 0; o >>= 1)
        s += __shfl_xor_sync(0xffffffffu, s, o);

    __shared__ double wsum[8];
    int lane = tid & 31;
    int wid = tid >> 5;
    if (lane == 0) wsum[wid] = s;
    __syncthreads();

    if (tid == 0) {
        double total = 0.0;
        #pragma unroll
        for (int w = 0; w < 8; w++) total += wsum[w];
        out[0] = (float)(total * INV_BATCH);
    }
}

extern "C" void kernel_launch(void* const* d_in, const int* in_sizes, int n_in,
                              void* d_out, int out_size) {
    const float* pred = (const float*)d_in[0];
    const float* tgt  = (const float*)d_in[1];
    float* out = (float*)d_out;

    yolo_loss_kernel<<<NBLOCKS, CELLS_PER_TILE>>>(pred, tgt);
    finalize_kernel<<<1, 256>>>(out);
}

// round 9
// speedup vs baseline: 1.0990x; 1.0990x over previous
#include <cuda_runtime.h>

#define CC 20
#define NCELLS (16384 * 7 * 7)         // 802816 = 6272 * 128
#define CELLS_PER_BLOCK 128
#define NBLOCKS (NCELLS / CELLS_PER_BLOCK)   // 6272
#define PRED_STRIDE 30
#define TGT_STRIDE 25
#define LAMBDA_COORD 5.0f
#define LAMBDA_NOOBJ 0.5f
#define EPS_W 1e-6f
#define IOU_EPS 1e-6f
#define INV_BATCH (1.0 / 16384.0)

#define PRED_F4_PER_BLOCK (CELLS_PER_BLOCK * PRED_STRIDE / 4)   // 960
#define TGT_F4_PER_BLOCK  (CELLS_PER_BLOCK * TGT_STRIDE  / 4)   // 800

// Per-block partial sums: written unconditionally every launch.
__device__ double g_partial[NBLOCKS];
// Arrival counter: 0 at module load; last block resets it to 0 each launch
// -> graph-replay idempotent.
__device__ unsigned int g_count;

__device__ __forceinline__ float iou_box(float ax, float ay, float aw, float ah,
                                         float bx, float by, float bw, float bh) {
    float ax1 = ax - aw * 0.5f, ax2 = ax + aw * 0.5f;
    float ay1 = ay - ah * 0.5f, ay2 = ay + ah * 0.5f;
    float bx1 = bx - bw * 0.5f, bx2 = bx + bw * 0.5f;
    float by1 = by - bh * 0.5f, by2 = by + bh * 0.5f;
    float iw = fmaxf(fminf(ax2, bx2) - fmaxf(ax1, bx1), 0.0f);
    float ih = fmaxf(fminf(ay2, by2) - fmaxf(ay1, by1), 0.0f);
    float inter = iw * ih;
    float area_a = fabsf(aw * ah);
    float area_b = fabsf(bw * bh);
    return inter / (area_a + area_b - inter + IOU_EPS);
}

__global__ void __launch_bounds__(CELLS_PER_BLOCK)
yolo_loss_kernel(const float* __restrict__ pred, const float* __restrict__ tgt,
                 float* __restrict__ out) {
    __shared__ float sp[CELLS_PER_BLOCK * PRED_STRIDE + 32];
    __shared__ float st[CELLS_PER_BLOCK * TGT_STRIDE + 32];

    const int tid = threadIdx.x;
    const int bid = blockIdx.x;

    // ---- Stage: fully coalesced float4 loads into smem ----
    {
        const float4* psrc = reinterpret_cast<const float4*>(
            pred + (size_t)bid * CELLS_PER_BLOCK * PRED_STRIDE);
        float4* pdst = reinterpret_cast<float4*>(sp);
        #pragma unroll
        for (int i = tid; i < PRED_F4_PER_BLOCK; i += CELLS_PER_BLOCK)
            pdst[i] = psrc[i];

        const float4* tsrc = reinterpret_cast<const float4*>(
            tgt + (size_t)bid * CELLS_PER_BLOCK * TGT_STRIDE);
        float4* tdst = reinterpret_cast<float4*>(st);
        #pragma unroll
        for (int i = tid; i < TGT_F4_PER_BLOCK; i += CELLS_PER_BLOCK)
            tdst[i] = tsrc[i];
    }
    __syncthreads();

    // ---- Compute: one thread = one cell, operands from smem ----
    const float* p = sp + tid * PRED_STRIDE;
    const float* t = st + tid * TGT_STRIDE;

    float cls = 0.0f;
    #pragma unroll
    for (int i = 0; i < CC; i++) {
        float d = p[i] - t[i];
        cls = fmaf(d, d, cls);
    }

    float b1x = p[20], b1y = p[21], b1w = p[22], b1h = p[23], b1c = p[24];
    float b2x = p[25], b2y = p[26], b2w = p[27], b2h = p[28], b2c = p[29];
    // tb = targets[..., 20:25] : note tb.x IS the objectness flag column
    float tbx = t[20], tby = t[21], tbw = t[22], tbh = t[23], tbc = t[24];
    float obj = (tbx == 1.0f) ? 1.0f : 0.0f;

    float iou1 = iou_box(b1x, b1y, b1w, b1h, tbx, tby, tbw, tbh);
    float iou2 = iou_box(b2x, b2y, b2w, b2h, tbx, tby, tbw, tbh);
    bool use1 = iou1 > iou2;

    float rx = use1 ? b1x : b2x;
    float ry = use1 ? b1y : b2y;
    float rw = use1 ? b1w : b2w;
    float rh = use1 ? b1h : b2h;
    float rc = use1 ? b1c : b2c;
    float other_conf = use1 ? b2c : b1c;

    float dx = rx - tbx;
    float dy = ry - tby;
    float dw = sqrtf(fmaxf(rw, EPS_W)) - sqrtf(fmaxf(tbw, EPS_W));
    float dh = sqrtf(fmaxf(rh, EPS_W)) - sqrtf(fmaxf(tbh, EPS_W));
    float coord = LAMBDA_COORD * (dx * dx + dy * dy + dw * dw + dh * dh);

    float dconf = rc - tbc;
    float obj_conf = dconf * dconf;
    float noobj_in = LAMBDA_NOOBJ * other_conf * other_conf;
    float noobj_out = LAMBDA_NOOBJ * (b1c * b1c + b2c * b2c);

    float loss = obj * (coord + obj_conf + cls + noobj_in) + (1.0f - obj) * noobj_out;

    // ---- Block reduction ----
    #pragma unroll
    for (int o = 16; o > 0; o >>= 1)
        loss += __shfl_xor_sync(0xffffffffu, loss, o);

    __shared__ float warp_sums[4];
    int lane = tid & 31;
    int wid = tid >> 5;
    if (lane == 0) warp_sums[wid] = loss;
    __syncthreads();

    __shared__ bool is_last;
    if (tid == 0) {
        float s = warp_sums[0] + warp_sums[1] + warp_sums[2] + warp_sums[3];
        g_partial[bid] = (double)s;
        __threadfence();                         // publish partial before count
        unsigned int prev = atomicAdd(&g_count, 1u);
        is_last = (prev == NBLOCKS - 1);
    }
    __syncthreads();

    // ---- Last block: reduce all partials, write output, reset counter ----
    if (is_last) {
        __threadfence();   // acquire: all partials visible
        // 6272 / 128 threads = 49 loads/thread over 4 independent chains.
        double a0 = 0.0, a1 = 0.0, a2 = 0.0, a3 = 0.0;
        int i = tid;
        #pragma unroll 4
        for (int k = 0; k < 48; k += 4) {
            a0 += g_partial[i];             i += CELLS_PER_BLOCK;
            a1 += g_partial[i];             i += CELLS_PER_BLOCK;
            a2 += g_partial[i];             i += CELLS_PER_BLOCK;
            a3 += g_partial[i];             i += CELLS_PER_BLOCK;
        }
        a0 += g_partial[i];                 // 49th
        double s = (a0 + a1) + (a2 + a3);

        #pragma unroll
        for (int o = 16; o > 0; o >>= 1)
            s += __shfl_xor_sync(0xffffffffu, s, o);

        __shared__ double wsum[4];
        if (lane == 0) wsum[wid] = s;
        __syncthreads();

        if (tid == 0) {
            double total = (wsum[0] + wsum[1]) + (wsum[2] + wsum[3]);
            out[0] = (float)(total * INV_BATCH);
            g_count = 0;                    // reset for next graph replay
        }
    }
}

extern "C" void kernel_launch(void* const* d_in, const int* in_sizes, int n_in,
                              void* d_out, int out_size) {
    const float* pred = (const float*)d_in[0];
    const float* tgt  = (const float*)d_in[1];
    float* out = (float*)d_out;

    yolo_loss_kernel<<<NBLOCKS, CELLS_PER_BLOCK>>>(pred, tgt, out);
}

// round 10
// speedup vs baseline: 1.4624x; 1.3307x over previous
#include <cuda_runtime.h>
#include <cstdint>

#define CC 20
#define NCELLS (16384 * 7 * 7)         // 802816 = 6272 * 128
#define CELLS_PER_BLOCK 128
#define NBLOCKS (NCELLS / CELLS_PER_BLOCK)   // 6272
#define PRED_STRIDE 30
#define TGT_STRIDE 25
#define LAMBDA_COORD 5.0f
#define LAMBDA_NOOBJ 0.5f
#define EPS_W 1e-6f
#define IOU_EPS 1e-6f
#define INV_BATCH (1.0 / 16384.0)

#define PRED_F4_PER_BLOCK (CELLS_PER_BLOCK * PRED_STRIDE / 4)   // 960
#define TGT_F4_PER_BLOCK  (CELLS_PER_BLOCK * TGT_STRIDE  / 4)   // 800

// Per-block partial sums: written unconditionally every launch -> no zeroing,
// no atomics, graph-replay idempotent.
__device__ double g_partial[NBLOCKS];

__device__ __forceinline__ void cp_async16(uint32_t smem_addr, const void* gptr) {
    asm volatile("cp.async.cg.shared.global [%0], [%1], 16;"
                 :: "r"(smem_addr), "l"(gptr) : "memory");
}

__device__ __forceinline__ float iou_box(float ax, float ay, float aw, float ah,
                                         float bx, float by, float bw, float bh) {
    float ax1 = ax - aw * 0.5f, ax2 = ax + aw * 0.5f;
    float ay1 = ay - ah * 0.5f, ay2 = ay + ah * 0.5f;
    float bx1 = bx - bw * 0.5f, bx2 = bx + bw * 0.5f;
    float by1 = by - bh * 0.5f, by2 = by + bh * 0.5f;
    float iw = fmaxf(fminf(ax2, bx2) - fmaxf(ax1, bx1), 0.0f);
    float ih = fmaxf(fminf(ay2, by2) - fmaxf(ay1, by1), 0.0f);
    float inter = iw * ih;
    float area_a = fabsf(aw * ah);
    float area_b = fabsf(bw * bh);
    return inter / (area_a + area_b - inter + IOU_EPS);
}

__global__ void __launch_bounds__(CELLS_PER_BLOCK, 8)
yolo_loss_kernel(const float* __restrict__ pred, const float* __restrict__ tgt) {
    __shared__ float sp[CELLS_PER_BLOCK * PRED_STRIDE];   // 15360 B
    __shared__ float st[CELLS_PER_BLOCK * TGT_STRIDE];    // 12800 B

    const int tid = threadIdx.x;
    const int bid = blockIdx.x;

    // ---- Stage: cp.async GMEM -> SMEM, no register round-trip ----
    {
        const float4* psrc = reinterpret_cast<const float4*>(
            pred + (size_t)bid * CELLS_PER_BLOCK * PRED_STRIDE);
        uint32_t sp_base = (uint32_t)__cvta_generic_to_shared(sp);
        #pragma unroll
        for (int i = tid; i < PRED_F4_PER_BLOCK; i += CELLS_PER_BLOCK)
            cp_async16(sp_base + i * 16, psrc + i);

        const float4* tsrc = reinterpret_cast<const float4*>(
            tgt + (size_t)bid * CELLS_PER_BLOCK * TGT_STRIDE);
        uint32_t st_base = (uint32_t)__cvta_generic_to_shared(st);
        #pragma unroll
        for (int i = tid; i < TGT_F4_PER_BLOCK; i += CELLS_PER_BLOCK)
            cp_async16(st_base + i * 16, tsrc + i);

        asm volatile("cp.async.commit_group;" ::: "memory");
        asm volatile("cp.async.wait_group 0;" ::: "memory");
    }
    __syncthreads();

    // ---- Compute: one thread = one cell, operands from smem ----
    const float* p = sp + tid * PRED_STRIDE;
    const float* t = st + tid * TGT_STRIDE;

    float cls = 0.0f;
    #pragma unroll
    for (int i = 0; i < CC; i++) {
        float d = p[i] - t[i];
        cls = fmaf(d, d, cls);
    }

    float b1x = p[20], b1y = p[21], b1w = p[22], b1h = p[23], b1c = p[24];
    float b2x = p[25], b2y = p[26], b2w = p[27], b2h = p[28], b2c = p[29];
    // tb = targets[..., 20:25] : note tb.x IS the objectness flag column
    float tbx = t[20], tby = t[21], tbw = t[22], tbh = t[23], tbc = t[24];
    float obj = (tbx == 1.0f) ? 1.0f : 0.0f;

    float iou1 = iou_box(b1x, b1y, b1w, b1h, tbx, tby, tbw, tbh);
    float iou2 = iou_box(b2x, b2y, b2w, b2h, tbx, tby, tbw, tbh);
    bool use1 = iou1 > iou2;

    float rx = use1 ? b1x : b2x;
    float ry = use1 ? b1y : b2y;
    float rw = use1 ? b1w : b2w;
    float rh = use1 ? b1h : b2h;
    float rc = use1 ? b1c : b2c;
    float other_conf = use1 ? b2c : b1c;

    float dx = rx - tbx;
    float dy = ry - tby;
    float dw = sqrtf(fmaxf(rw, EPS_W)) - sqrtf(fmaxf(tbw, EPS_W));
    float dh = sqrtf(fmaxf(rh, EPS_W)) - sqrtf(fmaxf(tbh, EPS_W));
    float coord = LAMBDA_COORD * (dx * dx + dy * dy + dw * dw + dh * dh);

    float dconf = rc - tbc;
    float obj_conf = dconf * dconf;
    float noobj_in = LAMBDA_NOOBJ * other_conf * other_conf;
    float noobj_out = LAMBDA_NOOBJ * (b1c * b1c + b2c * b2c);

    float loss = obj * (coord + obj_conf + cls + noobj_in) + (1.0f - obj) * noobj_out;

    // ---- Block reduction ----
    #pragma unroll
    for (int o = 16; o > 0; o >>= 1)
        loss += __shfl_xor_sync(0xffffffffu, loss, o);

    __shared__ float warp_sums[4];
    int lane = tid & 31;
    int wid = tid >> 5;
    if (lane == 0) warp_sums[wid] = loss;
    __syncthreads();

    if (wid == 0) {
        float s = (lane < 4) ? warp_sums[lane] : 0.0f;
        #pragma unroll
        for (int o = 2; o > 0; o >>= 1)
            s += __shfl_xor_sync(0xffffffffu, s, o);
        if (lane == 0)
            g_partial[bid] = (double)s;   // unconditional write, no atomic
    }
}

__global__ void __launch_bounds__(512)
finalize_kernel(float* out) {
    const int tid = threadIdx.x;

    // 6272 = 512*12 + 128. 12 strided loads per thread split across 4
    // independent accumulators (serial depth 3 -> latency overlapped).
    double a0 = 0.0, a1 = 0.0, a2 = 0.0, a3 = 0.0;
    #pragma unroll
    for (int k = 0; k < 12; k += 4) {
        a0 += g_partial[tid + (k + 0) * 512];
        a1 += g_partial[tid + (k + 1) * 512];
        a2 += g_partial[tid + (k + 2) * 512];
        a3 += g_partial[tid + (k + 3) * 512];
    }
    if (tid < 128) a0 += g_partial[6144 + tid];
    double s = (a0 + a1) + (a2 + a3);

    #pragma unroll
    for (int o = 16; o > 0; o >>= 1)
        s += __shfl_xor_sync(0xffffffffu, s, o);

    __shared__ double wsum[16];
    int lane = tid & 31;
    int wid = tid >> 5;
    if (lane == 0) wsum[wid] = s;
    __syncthreads();

    if (tid == 0) {
        double total = 0.0;
        #pragma unroll
        for (int w = 0; w < 16; w++) total += wsum[w];
        out[0] = (float)(total * INV_BATCH);
    }
}

extern "C" void kernel_launch(void* const* d_in, const int* in_sizes, int n_in,
                              void* d_out, int out_size) {
    const float* pred = (const float*)d_in[0];
    const float* tgt  = (const float*)d_in[1];
    float* out = (float*)d_out;

    yolo_loss_kernel<<<NBLOCKS, CELLS_PER_BLOCK>>>(pred, tgt);
    finalize_kernel<<<1, 512>>>(out);
}